// round 15
// baseline (speedup 1.0000x reference)
#include <cuda_runtime.h>
#include <cstddef>

#define HIDN   512
#define HEADS  8
#define HD     64
#define BB     2
#define LQ     384
#define LKK    384
#define MROWS  (BB*LQ)   // 768

// ---------------- scratch (no allocations allowed) ----------------
__device__ float g_Wq2[HIDN*HIDN];
__device__ float g_Wk2[HIDN*HIDN];
__device__ float g_bq2[HIDN];
__device__ float g_bk2[HIDN];
__device__ float g_qW[MROWS*HIDN];
__device__ float g_kU[MROWS*HIDN];
__device__ float g_V [MROWS*HIDN];
__device__ float g_xh[MROWS*HIDN];

// ---------------- K0: fold Ww/Wu into Wq/Wk ----------------
// Wq2[i, h*64+j] = sum_t Wq[i, h*64+t] * Ww[t, j]
// bq2[h*64+j]    = sum_t bq[h*64+t]   * Ww[t, j] + bw[j]
__global__ void __launch_bounds__(512) fold_kernel(
    const float* __restrict__ Wq, const float* __restrict__ bq,
    const float* __restrict__ Ww, const float* __restrict__ bw,
    const float* __restrict__ Wk, const float* __restrict__ bk,
    const float* __restrict__ Wu, const float* __restrict__ bu)
{
    int i = blockIdx.x;
    bool second = (blockIdx.y != 0);
    const float* Win = second ? Wk : Wq;
    const float* S   = second ? Wu : Ww;
    float* Wout      = second ? g_Wk2 : g_Wq2;

    int jf = threadIdx.x;          // 0..511
    int h = jf >> 6, j = jf & 63;
    const float* wrow = Win + (size_t)i*HIDN + h*HD;
    float acc = 0.f;
    #pragma unroll 8
    for (int t = 0; t < HD; ++t) acc = fmaf(wrow[t], S[t*HD + j], acc);
    Wout[(size_t)i*HIDN + jf] = acc;

    if (i == 0) {
        const float* bin = second ? bk : bq;
        const float* bs  = second ? bu : bw;
        float* bout      = second ? g_bk2 : g_bq2;
        float bacc = bs[j];
        #pragma unroll 8
        for (int t = 0; t < HD; ++t) bacc = fmaf(bin[h*HD + t], S[t*HD + j], bacc);
        bout[jf] = bacc;
    }
}

// ---------------- shared fp32 GEMM tile (64x64, Kc=16, 256 thr, 4x4/thr) ----------------
__device__ __forceinline__ void gemm_tile_64(
    const float* __restrict__ A, int lda,
    const float* __restrict__ Bm, int ldb,
    const float* __restrict__ bias,   // may be nullptr
    float* __restrict__ C, int ldc,
    int K, int m0, int n0)
{
    __shared__ float As[16][68];   // [kc][m], padded to dodge store conflicts
    __shared__ float Bs[16][64];   // [kc][n]
    const int t  = threadIdx.x;    // 256 threads
    const int tx = t & 15, ty = t >> 4;

    float acc[4][4] = {};
    for (int k0 = 0; k0 < K; k0 += 16) {
        #pragma unroll
        for (int i = 0; i < 4; ++i) {
            int idx = t + i*256;                 // 0..1023
            int m  = idx >> 4, kc  = idx & 15;   // A: coalesced-ish 64B rows
            As[kc][m] = A[(size_t)(m0+m)*lda + k0 + kc];
            int n  = idx & 63, kc2 = idx >> 6;   // B: fully coalesced
            Bs[kc2][n] = Bm[(size_t)(k0+kc2)*ldb + n0 + n];
        }
        __syncthreads();
        #pragma unroll
        for (int kc = 0; kc < 16; ++kc) {
            float4 av = *(const float4*)&As[kc][ty*4];
            float4 bv = *(const float4*)&Bs[kc][tx*4];
            float a4[4] = {av.x, av.y, av.z, av.w};
            float b4[4] = {bv.x, bv.y, bv.z, bv.w};
            #pragma unroll
            for (int i = 0; i < 4; ++i)
                #pragma unroll
                for (int j = 0; j < 4; ++j)
                    acc[i][j] = fmaf(a4[i], b4[j], acc[i][j]);
        }
        __syncthreads();
    }
    #pragma unroll
    for (int i = 0; i < 4; ++i) {
        int m = m0 + ty*4 + i;
        #pragma unroll
        for (int j = 0; j < 4; ++j) {
            int n = n0 + tx*4 + j;
            float bb = bias ? bias[n] : 0.f;
            C[(size_t)m*ldc + n] = acc[i][j] + bb;
        }
    }
}

// ---------------- K1: three projections in one launch (z selects job) ----------------
// qW = query @ Wq2 + bq2 ; kU = key @ Wk2 + bk2 ; V = value @ Wv + bv
__global__ void __launch_bounds__(256) proj_kernel(
    const float* __restrict__ q, const float* __restrict__ k, const float* __restrict__ v,
    const float* __restrict__ Wv, const float* __restrict__ bv)
{
    int z = blockIdx.z;
    const float* A    = (z == 0) ? q     : (z == 1) ? k     : v;
    const float* Bm   = (z == 0) ? g_Wq2 : (z == 1) ? g_Wk2 : Wv;
    const float* bias = (z == 0) ? g_bq2 : (z == 1) ? g_bk2 : bv;
    float* C          = (z == 0) ? g_qW  : (z == 1) ? g_kU  : g_V;
    gemm_tile_64(A, HIDN, Bm, HIDN, bias, C, HIDN, HIDN,
                 blockIdx.y*64, blockIdx.x*64);
}

// ---------------- K2: energy + softmax -> attention ----------------
// block = (q-tile of 16, one (b,h)); 512 threads = 16 warps, warp-per-query,
// lane owns 12 keys (12*32 = 384). kU head slice cached in SMEM, 65-float
// padded rows -> conflict-free per-lane access.
__global__ void __launch_bounds__(512) energy_softmax_kernel(
    const float* __restrict__ vv, float* __restrict__ att)
{
    extern __shared__ float smf[];
    float* ku_s = smf;                       // 384*65
    float* qw_s = smf + LKK*65;              // 16*64
    float* vv_s = qw_s + 16*64;              // 64

    int qt = blockIdx.x;                     // 0..23
    int bh = blockIdx.y;                     // 0..15
    int b = bh >> 3, h = bh & 7;
    int tid = threadIdx.x;

    const float* kU_b = g_kU + ((size_t)b*LKK)*HIDN + h*HD;
    for (int idx = tid; idx < LKK*HD; idx += 512) {
        int k = idx >> 6, d = idx & 63;
        ku_s[k*65 + d] = kU_b[(size_t)k*HIDN + d];
    }
    const float* qW_b = g_qW + ((size_t)b*LQ + qt*16)*HIDN + h*HD;
    for (int idx = tid; idx < 16*64; idx += 512) {
        int qq = idx >> 6, d = idx & 63;
        qw_s[idx] = qW_b[(size_t)qq*HIDN + d];
    }
    if (tid < 64) vv_s[tid] = vv[tid];
    __syncthreads();

    int w = tid >> 5, lane = tid & 31;
    const float* qw_row = qw_s + w*64;
    const float* kb = ku_s + lane*65;

    float e[12];
    #pragma unroll
    for (int j = 0; j < 12; ++j) e[j] = 0.f;

    #pragma unroll 4
    for (int d = 0; d < 64; ++d) {
        float qd = qw_row[d];
        float vd = vv_s[d];
        #pragma unroll
        for (int j = 0; j < 12; ++j) {
            float xv = qd + kb[j*2080 + d];   // (j*32)*65
            float th;
            asm("tanh.approx.f32 %0, %1;" : "=f"(th) : "f"(xv));
            e[j] = fmaf(vd, th, e[j]);
        }
    }

    // scale by 1/sqrt(hd) and softmax over 384 keys (regs + warp shuffles)
    float m = -1e30f;
    #pragma unroll
    for (int j = 0; j < 12; ++j) { e[j] *= 0.125f; m = fmaxf(m, e[j]); }
    #pragma unroll
    for (int o = 16; o > 0; o >>= 1) m = fmaxf(m, __shfl_xor_sync(0xffffffffu, m, o));
    float s = 0.f;
    float p[12];
    #pragma unroll
    for (int j = 0; j < 12; ++j) { p[j] = __expf(e[j] - m); s += p[j]; }
    #pragma unroll
    for (int o = 16; o > 0; o >>= 1) s += __shfl_xor_sync(0xffffffffu, s, o);
    float inv = __frcp_rn(s);

    int q = qt*16 + w;
    float* arow = att + ((size_t)bh*LQ + q)*LKK;
    #pragma unroll
    for (int j = 0; j < 12; ++j) arow[j*32 + lane] = p[j] * inv;
}

// ---------------- K3: x_h = attention @ V  (batched over b,h) ----------------
__global__ void __launch_bounds__(256) av_kernel(const float* __restrict__ att)
{
    int z = blockIdx.z;            // 0..15 = b*8+h
    int b = z >> 3, h = z & 7;
    const float* A  = att  + (size_t)z*LQ*LKK;               // [384,384], lda=384
    const float* Bm = g_V  + ((size_t)b*LKK)*HIDN + h*HD;    // [384,64],  ldb=512
    float*       C  = g_xh + ((size_t)b*LQ )*HIDN + h*HD;    // [384,64],  ldc=512
    gemm_tile_64(A, LKK, Bm, HIDN, nullptr, C, HIDN, LKK,
                 blockIdx.y*64, 0);
}

// ---------------- K4: x = xh @ Wo + bo ----------------
__global__ void __launch_bounds__(256) out_kernel(
    const float* __restrict__ Wo, const float* __restrict__ bo,
    float* __restrict__ out_x)
{
    gemm_tile_64(g_xh, HIDN, Wo, HIDN, bo, out_x, HIDN, HIDN,
                 blockIdx.y*64, blockIdx.x*64);
}

// ---------------- launch ----------------
extern "C" void kernel_launch(void* const* d_in, const int* in_sizes, int n_in,
                              void* d_out, int out_size)
{
    (void)in_sizes; (void)n_in; (void)out_size;
    const float* query = (const float*)d_in[0];
    const float* key_  = (const float*)d_in[1];
    const float* value = (const float*)d_in[2];
    const float* Wq = (const float*)d_in[3];
    const float* bq = (const float*)d_in[4];
    const float* Wk = (const float*)d_in[5];
    const float* bk = (const float*)d_in[6];
    const float* Wv = (const float*)d_in[7];
    const float* bv = (const float*)d_in[8];
    const float* Ww = (const float*)d_in[9];
    const float* bw = (const float*)d_in[10];
    const float* Wu = (const float*)d_in[11];
    const float* bu = (const float*)d_in[12];
    const float* vv = (const float*)d_in[13];
    const float* Wo = (const float*)d_in[14];
    const float* bo = (const float*)d_in[15];

    float* out     = (float*)d_out;
    float* out_x   = out;                          // [2,384,512]
    float* out_att = out + (size_t)MROWS*HIDN;     // [2,8,384,384]

    // K0: fold per-head Ww/Wu into the Q/K projection weights
    fold_kernel<<<dim3(512, 2), 512>>>(Wq, bq, Ww, bw, Wk, bk, Wu, bu);

    // K1: qW / kU / V projections in one grid (288 blocks)
    proj_kernel<<<dim3(8, 12, 3), 256>>>(query, key_, value, Wv, bv);

    // K2: additive energy + softmax -> attention (written straight to d_out)
    size_t esmem = (size_t)(LKK*65 + 16*64 + 64) * sizeof(float); // ~104 KB
    cudaFuncSetAttribute(energy_softmax_kernel,
                         cudaFuncAttributeMaxDynamicSharedMemorySize, (int)esmem);
    energy_softmax_kernel<<<dim3(24, 16), 512, esmem>>>(vv, out_att);

    // K3: attention @ V
    av_kernel<<<dim3(1, 6, 16), 256>>>(out_att);

    // K4: output projection
    out_kernel<<<dim3(8, 12), 256>>>(Wo, bo, out_x);
}